// round 6
// baseline (speedup 1.0000x reference)
#include <cuda_runtime.h>
#include <cuda_bf16.h>

#define DIM 128

// ---------------------------------------------------------------------------
// Kernel A (sub2): one block (256 thr = 8 warps) per type node c.
//   out[rc] = emb[rc] + sum_j emb[left_specific[sub2_row[...]]] + (n_ent-deg2)
// ---------------------------------------------------------------------------
__global__ void sub2_kernel(const float* __restrict__ emb,
                            const int* __restrict__ sub2_row,
                            const int* __restrict__ left_specific,
                            const int* __restrict__ right_common,
                            float* __restrict__ out,
                            int n_ent, int deg2) {
    extern __shared__ char smem_raw[];
    int*    rows = (int*)smem_raw;                                  // [deg2]
    float4* red  = (float4*)(smem_raw + ((deg2 * 4 + 127) & ~127)); // [8][32]

    const int c     = blockIdx.x;
    const int w     = threadIdx.x >> 5;
    const int lane  = threadIdx.x & 31;
    const int nwarp = blockDim.x >> 5;

    for (int j = threadIdx.x; j < deg2; j += blockDim.x)
        rows[j] = left_specific[__ldg(sub2_row + (size_t)c * deg2 + j)];
    __syncthreads();

    float4 acc = make_float4(0.f, 0.f, 0.f, 0.f);
    for (int j = w; j < deg2; j += nwarp) {
        const float4 v = __ldg((const float4*)(emb + (size_t)rows[j] * DIM) + lane);
        acc.x += v.x; acc.y += v.y; acc.z += v.z; acc.w += v.w;
    }
    red[w * 32 + lane] = acc;
    __syncthreads();

    if (w == 0) {
        float4 s = red[lane];
#pragma unroll
        for (int k = 1; k < 8; ++k) {
            const float4 v = red[k * 32 + lane];
            s.x += v.x; s.y += v.y; s.z += v.z; s.w += v.w;
        }
        const int   rc = right_common[c];
        const float a  = (float)(n_ent - deg2);
        const float4 e = __ldg((const float4*)(emb + (size_t)rc * DIM) + lane);
        float4 r;
        r.x = e.x + s.x + a; r.y = e.y + s.y + a;
        r.z = e.z + s.z + a; r.w = e.w + s.w + a;
        ((float4*)(out + (size_t)rc * DIM) + lane)[0] = r;
    }
}

// ---------------------------------------------------------------------------
// Kernel B (sub3, deg3==4): one block per residue class r (= c mod n_typ).
// Entities c = r, r+n_typ, r+2*n_typ, ... share identical sub3 index lists
// (verified per-entity via int4 compare against the class representative).
// Warp 0 computes the shared type-row sum ONCE into smem; all warps then
// stream entity rows: __ldcs read -> scale -> __stcs write, no gathers.
//   out[rs] = emb[rs] * (1 - (W + (n_typ-4)) / 5)
// ---------------------------------------------------------------------------
__global__ void __launch_bounds__(256) sub3_kernel_d4(
        const float* __restrict__ emb,
        const int* __restrict__ sub3_row,
        const int* __restrict__ left_common,
        const int* __restrict__ right_specific,
        float* out,
        int n_ent, int n_typ) {
    __shared__ float4 Wsh[32];
    __shared__ int4   rep;

    const int r = blockIdx.x;
    if (r >= n_ent) return;
    const int lane = threadIdx.x & 31;
    const int w    = threadIdx.x >> 5;

    if (threadIdx.x == 0)
        rep = *(const int4*)(sub3_row + (size_t)r * 4);
    __syncthreads();

    if (w == 0) {
        const int ridx[4] = {rep.x, rep.y, rep.z, rep.w};
        float4 acc = make_float4(0.f, 0.f, 0.f, 0.f);
#pragma unroll
        for (int j = 0; j < 4; ++j) {
            const int node = __ldg(left_common + ridx[j]);
            const float4 v = __ldg((const float4*)(out + (size_t)node * DIM) + lane);
            acc.x += v.x; acc.y += v.y; acc.z += v.z; acc.w += v.w;
        }
        Wsh[lane] = acc;
    }
    __syncthreads();

    const float  addc = (float)(n_typ - 4);
    const float  inv  = 0.2f;
    const float4 Wv   = Wsh[lane];
    const int    nq   = (n_ent - r + n_typ - 1) / n_typ;  // entities in class

    // Warp w handles q = w*4 + iter*32 + {0..3}: 4 independent entities per
    // iteration -> 4 streaming row loads in flight per warp.
    for (int qb = w * 4; qb < nq; qb += 32) {
        int    rs[4];
        int4   idx[4];
        float4 ev[4];
#pragma unroll
        for (int i = 0; i < 4; ++i) {
            const int q = qb + i;
            if (q < nq) {
                const int c = r + q * n_typ;
                rs[i]  = __ldg(right_specific + c);
                idx[i] = __ldg((const int4*)(sub3_row) + c);
            }
        }
#pragma unroll
        for (int i = 0; i < 4; ++i) {
            if (qb + i < nq)
                ev[i] = __ldcs((const float4*)(emb + (size_t)rs[i] * DIM) + lane);
        }
#pragma unroll
        for (int i = 0; i < 4; ++i) {
            if (qb + i >= nq) break;
            float4 wv;
            if (idx[i].x == rep.x && idx[i].y == rep.y &&
                idx[i].z == rep.z && idx[i].w == rep.w) {
                wv = Wv;
            } else {
                // Rare fallback: direct gathers of (L2-resident) type rows.
                wv = make_float4(0.f, 0.f, 0.f, 0.f);
                const int fidx[4] = {idx[i].x, idx[i].y, idx[i].z, idx[i].w};
#pragma unroll
                for (int j = 0; j < 4; ++j) {
                    const int node = __ldg(left_common + fidx[j]);
                    const float4 v = __ldg((const float4*)(out + (size_t)node * DIM) + lane);
                    wv.x += v.x; wv.y += v.y; wv.z += v.z; wv.w += v.w;
                }
            }
            float4 o;
            o.x = ev[i].x * (1.0f - (wv.x + addc) * inv);
            o.y = ev[i].y * (1.0f - (wv.y + addc) * inv);
            o.z = ev[i].z * (1.0f - (wv.z + addc) * inv);
            o.w = ev[i].w * (1.0f - (wv.w + addc) * inv);
            __stcs((float4*)(out + (size_t)rs[i] * DIM) + lane, o);
        }
    }
}

// Generic fallback (any deg3), one warp per entity.
__global__ void sub3_kernel_gen(const float* __restrict__ emb,
                                const int* __restrict__ sub3_row,
                                const int* __restrict__ left_common,
                                const int* __restrict__ right_specific,
                                float* out,
                                int n_ent, int n_typ, int deg3) {
    const int gw   = (int)((blockIdx.x * (size_t)blockDim.x + threadIdx.x) >> 5);
    const int lane = threadIdx.x & 31;
    if (gw >= n_ent) return;

    const float addc = (float)(n_typ - deg3);
    const float inv  = 1.0f / (float)(1 + deg3);

    float4 acc = make_float4(0.f, 0.f, 0.f, 0.f);
    const int* rbase = sub3_row + (size_t)gw * deg3;
    for (int j = 0; j < deg3; ++j) {
        const int node = __ldg(left_common + __ldg(rbase + j));
        const float4 v = __ldg((const float4*)(out + (size_t)node * DIM) + lane);
        acc.x += v.x; acc.y += v.y; acc.z += v.z; acc.w += v.w;
    }
    const int   rs = __ldg(right_specific + gw);
    const float4 e = __ldcs((const float4*)(emb + (size_t)rs * DIM) + lane);
    float4 o;
    o.x = e.x * (1.0f - (acc.x + addc) * inv);
    o.y = e.y * (1.0f - (acc.y + addc) * inv);
    o.z = e.z * (1.0f - (acc.z + addc) * inv);
    o.w = e.w * (1.0f - (acc.w + addc) * inv);
    __stcs((float4*)(out + (size_t)rs * DIM) + lane, o);
}

extern "C" void kernel_launch(void* const* d_in, const int* in_sizes, int n_in,
                              void* d_out, int out_size) {
    const float* emb            = (const float*)d_in[0];
    const int*   sub2_row       = (const int*)d_in[1];
    const int*   sub3_row       = (const int*)d_in[3];
    const int*   left_specific  = (const int*)d_in[5];
    const int*   right_common   = (const int*)d_in[6];
    const int*   left_common    = (const int*)d_in[7];
    const int*   right_specific = (const int*)d_in[8];
    float*       out            = (float*)d_out;

    const int n_ent = in_sizes[5];                 // 200000
    const int n_typ = in_sizes[7];                 // 1000
    const int deg2  = in_sizes[1] / n_typ;         // 64
    const int deg3  = in_sizes[3] / n_ent;         // 4

    // Phase 1: updated type rows -> out[type rows]
    const int smem = ((deg2 * 4 + 127) & ~127) + 8 * 32 * (int)sizeof(float4);
    sub2_kernel<<<n_typ, 256, smem>>>(
        emb, sub2_row, left_specific, right_common, out, n_ent, deg2);

    // Phase 2: updated entity rows (reads phase-1 type rows, stream-ordered).
    if (deg3 == 4) {
        sub3_kernel_d4<<<n_typ, 256>>>(
            emb, sub3_row, left_common, right_specific, out, n_ent, n_typ);
    } else {
        const int wpb = 8;
        const int blocks = (n_ent + wpb - 1) / wpb;
        sub3_kernel_gen<<<blocks, wpb * 32>>>(
            emb, sub3_row, left_common, right_specific, out, n_ent, n_typ, deg3);
    }
}